// round 6
// baseline (speedup 1.0000x reference)
#include <cuda_runtime.h>
#include <math.h>
#include <stdint.h>

// Problem constants
#define BB_    8
#define LL_    512
#define HEADS_ 12
#define HS_    64
#define HID_   768
#define OD_    1536          // HEADS*2*HS
#define M1_    (BB_*LL_)     // 4096
#define BH_    (BB_*HEADS_)  // 96
#define NEG_INF_F (-3.4028234663852886e38f)

// Scratch (device globals — no allocations allowed)
__device__ uint8_t g_Af8[M1_ * HID_];     // inputs e4m3 [4096][768]
__device__ uint8_t g_WTf8[OD_ * HID_];    // W^T e4m3 [1536][768]
__device__ uint8_t g_q8[BH_ * LL_ * HS_]; // [b*h][l][d] e4m3
__device__ uint8_t g_k8[BH_ * LL_ * HS_];
__device__ float g_sin[LL_ * 32];
__device__ float g_cos[LL_ * 32];

// ---------------------------------------------------------------------------
// PTX helpers (portable ISA only — compute_103 target has no 'a' features)
// ---------------------------------------------------------------------------
__device__ __forceinline__ uint32_t smem_u32(const void* p) {
    return (uint32_t)__cvta_generic_to_shared(p);
}
__device__ __forceinline__ void cp16(uint32_t s, const void* g) {
    asm volatile("cp.async.cg.shared.global [%0], [%1], 16;\n" :: "r"(s), "l"(g));
}
#define CP_COMMIT() asm volatile("cp.async.commit_group;\n")
#define CP_WAIT0()  asm volatile("cp.async.wait_group 0;\n")
#define CP_WAIT2()  asm volatile("cp.async.wait_group 2;\n")

// cvt packs first source into the HIGH byte: d = {hi, lo}
__device__ __forceinline__ uint16_t f2e4m3x2(float hi, float lo) {
    uint16_t r;
    asm("cvt.rn.satfinite.e4m3x2.f32 %0, %1, %2;\n" : "=h"(r) : "f"(hi), "f"(lo));
    return r;
}

__device__ __forceinline__ void ldsm_x4(uint32_t* r, const void* p) {
    uint32_t a = smem_u32(p);
    asm volatile("ldmatrix.sync.aligned.m8n8.x4.shared.b16 {%0,%1,%2,%3},[%4];"
                 : "=r"(r[0]), "=r"(r[1]), "=r"(r[2]), "=r"(r[3]) : "r"(a));
}

// D += A(m16k32) * B(k32n8), e4m3 in, f32 accum
__device__ __forceinline__ void mma_fp8(float* d, const uint32_t* a, const uint32_t* b) {
    asm volatile(
        "mma.sync.aligned.m16n8k32.row.col.f32.e4m3.e4m3.f32 "
        "{%0,%1,%2,%3},{%4,%5,%6,%7},{%8,%9},{%0,%1,%2,%3};\n"
        : "+f"(d[0]), "+f"(d[1]), "+f"(d[2]), "+f"(d[3])
        : "r"(a[0]), "r"(a[1]), "r"(a[2]), "r"(a[3]), "r"(b[0]), "r"(b[1]));
}

// ---------------------------------------------------------------------------
// Kernel 0: merged prep — A->e4m3, RoPE tables, W transpose->e4m3
// ---------------------------------------------------------------------------
#define NA4_   ((M1_ * HID_) / 4)       // 786432
#define NT_    (LL_ * 32)               // 16384
#define NPREP_ ((NA4_ + NT_ + 255) / 256)   // 3136 blocks for part 1
#define NTRB_  ((OD_ / 32) * (HID_ / 32))   // 1152 transpose blocks

__global__ void __launch_bounds__(256)
prep_all(const float* __restrict__ A, const float* __restrict__ W) {
    const int bid = blockIdx.x;
    if (bid < NPREP_) {
        int idx = bid * 256 + threadIdx.x;
        if (idx < NA4_) {
            float4 v = ((const float4*)A)[idx];
            uint32_t lo = f2e4m3x2(v.y, v.x);
            uint32_t hi = f2e4m3x2(v.w, v.z);
            ((uint32_t*)g_Af8)[idx] = lo | (hi << 16);
        } else if (idx < NA4_ + NT_) {
            int j = idx - NA4_;
            int l = j >> 5;
            int p = j & 31;
            float inv = powf(10000.0f, -(float)p / 32.0f);
            float ang = (float)l * inv;
            g_sin[j] = sinf(ang);
            g_cos[j] = cosf(ang);
        }
        return;
    }
    // W [768][1536] fp32 -> g_WTf8 [1536][768] e4m3, 32x32 tiles
    __shared__ float tile[32][33];
    const int b2 = bid - NPREP_;
    const int bx = b2 % (OD_ / 32);
    const int by = b2 / (OD_ / 32);
    const int c  = threadIdx.x & 31;
    const int r4 = threadIdx.x >> 5;
    #pragma unroll
    for (int i = 0; i < 4; i++) {
        int r = r4 * 4 + i;
        tile[r][c] = W[(size_t)(by * 32 + r) * OD_ + bx * 32 + c];
    }
    __syncthreads();
    #pragma unroll
    for (int i = 0; i < 4; i++) {
        int r = r4 * 4 + i;
        g_WTf8[(size_t)(bx * 32 + r) * HID_ + by * 32 + c] =
            (uint8_t)(f2e4m3x2(0.0f, tile[c][r]) & 0xFF);
    }
}

// ---------------------------------------------------------------------------
// Kernel 1: X = A @ W + b (4096x1536, K=768), fp8 mma m16n8k32.
// 128x128 block, BK=64, 8 warps (4x2), warp tile 32x64.
// 4-stage cp.async ring, software-pipelined fragments.
// ---------------------------------------------------------------------------
#define A8_STRIDE   80
#define TILE8_BYTES (128 * A8_STRIDE)      // 10240
#define STAGE8      (2 * TILE8_BYTES)      // 20480
#define G1_DSMEM    (4 * STAGE8)           // 81920

#define MMA4(AF, BF, NT) do { \
    mma_fp8(acc[0][2*(NT)],     (AF)[0], &(BF)[0]); \
    mma_fp8(acc[0][2*(NT) + 1], (AF)[0], &(BF)[2]); \
    mma_fp8(acc[1][2*(NT)],     (AF)[1], &(BF)[0]); \
    mma_fp8(acc[1][2*(NT) + 1], (AF)[1], &(BF)[2]); \
} while (0)

__global__ void __launch_bounds__(256, 2)
gemm1_fp8(const float* __restrict__ bias) {
    extern __shared__ uint8_t sm8[];

    const int t    = threadIdx.x;
    const int lane = t & 31;
    const int warp = t >> 5;
    const int g    = lane >> 2;
    const int tig  = lane & 3;
    const int wm   = warp >> 1;     // 0..3
    const int wn   = warp & 1;      // 0..1
    const int m0   = blockIdx.y * 128;
    const int n0   = blockIdx.x * 128;

    float acc[2][8][4];
    #pragma unroll
    for (int mt = 0; mt < 2; mt++)
        #pragma unroll
        for (int j = 0; j < 8; j++)
            #pragma unroll
            for (int c = 0; c < 4; c++) acc[mt][j][c] = 0.0f;

    auto load_tile = [&](int buf, int k0) {
        uint8_t* as = sm8 + buf * STAGE8;
        uint8_t* bs = as + TILE8_BYTES;
        #pragma unroll
        for (int i = 0; i < 2; i++) {
            int ch = t + 256 * i;
            int r = ch >> 2;
            int cc = (ch & 3) * 16;
            cp16(smem_u32(as + r * A8_STRIDE + cc),
                 g_Af8 + (size_t)(m0 + r) * HID_ + k0 + cc);
        }
        #pragma unroll
        for (int i = 0; i < 2; i++) {
            int ch = t + 256 * i;
            int r = ch >> 2;
            int cc = (ch & 3) * 16;
            cp16(smem_u32(bs + r * A8_STRIDE + cc),
                 g_WTf8 + (size_t)(n0 + r) * HID_ + k0 + cc);
        }
        CP_COMMIT();
    };

    load_tile(0, 0);
    load_tile(1, 64);
    load_tile(2, 128);

    // Per-thread fixed smem offsets for fragment loads
    const int a_row  = lane & 15;
    const int a_coff = (lane >> 4) * 16;
    const int b_row  = (lane & 7) + 8 * (lane >> 4);
    const int b_coff = 16 * ((lane >> 3) & 1);
    const int aoff0  = (wm * 32 + a_row) * A8_STRIDE + a_coff;          // mt=0
    const int aoff1  = aoff0 + 16 * A8_STRIDE;                          // mt=1
    const int boffs0 = (wn * 64 + b_row) * A8_STRIDE + b_coff;          // nt=0
    // nt stride = 16 rows = 16*A8_STRIDE

    for (int kt = 0; kt < 12; kt++) {
        const int buf = kt & 3;
        CP_WAIT2();
        __syncthreads();
        if (kt + 3 < 12) load_tile((kt + 3) & 3, (kt + 3) * 64);
        else             CP_COMMIT();   // keep group count uniform for WAIT2

        const uint8_t* as = sm8 + buf * STAGE8;
        const uint8_t* bs = as + TILE8_BYTES;

        uint32_t afA[2][4], afB[2][4], bfA[4], bfB[4];

        // kk=0 prologue
        ldsm_x4(afA[0], as + aoff0);
        ldsm_x4(afA[1], as + aoff1);
        ldsm_x4(bfA,    bs + boffs0);
        // kk=0 body (rolling bf)
        ldsm_x4(bfB, bs + boffs0 + 1 * 16 * A8_STRIDE);  MMA4(afA, bfA, 0);
        ldsm_x4(bfA, bs + boffs0 + 2 * 16 * A8_STRIDE);  MMA4(afA, bfB, 1);
        ldsm_x4(bfB, bs + boffs0 + 3 * 16 * A8_STRIDE);  MMA4(afA, bfA, 2);
        // prefetch kk=1 A + first B under last kk=0 mma
        ldsm_x4(afB[0], as + aoff0 + 32);
        ldsm_x4(afB[1], as + aoff1 + 32);
        ldsm_x4(bfA,    bs + boffs0 + 32);               MMA4(afA, bfB, 3);
        // kk=1 body
        ldsm_x4(bfB, bs + boffs0 + 32 + 1 * 16 * A8_STRIDE); MMA4(afB, bfA, 0);
        ldsm_x4(bfA, bs + boffs0 + 32 + 2 * 16 * A8_STRIDE); MMA4(afB, bfB, 1);
        ldsm_x4(bfB, bs + boffs0 + 32 + 3 * 16 * A8_STRIDE); MMA4(afB, bfA, 2);
        MMA4(afB, bfB, 3);
    }

    // Epilogue: bias + RoPE + e4m3 scatter to g_q8/g_k8 ([b*h][l][d])
    #pragma unroll
    for (int mt = 0; mt < 2; mt++) {
        #pragma unroll
        for (int half = 0; half < 2; half++) {
            const int m  = m0 + wm * 32 + mt * 16 + g + half * 8;
            const int l  = m & (LL_ - 1);
            const int b_ = m >> 9;
            #pragma unroll
            for (int j = 0; j < 8; j++) {
                const int n = n0 + wn * 64 + j * 8 + 2 * tig;   // even col
                float e = acc[mt][j][half * 2 + 0] + bias[n];
                float o = acc[mt][j][half * 2 + 1] + bias[n + 1];
                const int h  = n >> 7;
                const int qk = (n >> 6) & 1;
                const int d  = n & 63;
                const int p  = d >> 1;
                const float s  = g_sin[l * 32 + p];
                const float co = g_cos[l * 32 + p];
                uint16_t v = f2e4m3x2(e * s + o * co, e * co - o * s);
                uint8_t* dst = (qk ? g_k8 : g_q8)
                    + ((size_t)(b_ * HEADS_ + h) * LL_ + l) * HS_ + d;
                *(uint16_t*)dst = v;
            }
        }
    }
}

// ---------------------------------------------------------------------------
// Kernel 2: logits = (q.k)/8, masked; fp8 mma. 128x128 tile, 256 threads,
// 8 warps (2x4), warp tile 64x32. Per-block mask specialization:
//   tm > tn : pure neg-inf fill;  tm < tn : no diagonal compare;
//   tm == tn: full compare.
// ---------------------------------------------------------------------------
#define QK8_STRIDE 80

__global__ void __launch_bounds__(256)
attn_logits_fp8(const int* __restrict__ am, float* __restrict__ out) {
    const int bh = blockIdx.z;
    const int tm = blockIdx.y;
    const int tn = blockIdx.x;
    const int t  = threadIdx.x;
    const int b_ = bh / HEADS_;
    const int m0 = tm * 128;
    const int n0 = tn * 128;
    float* obase = out + (size_t)bh * LL_ * LL_;

    if (tm > tn) {
        const float4 nv = make_float4(NEG_INF_F, NEG_INF_F, NEG_INF_F, NEG_INF_F);
        #pragma unroll
        for (int i = t; i < 4096; i += 256) {          // 128*128/4 float4s
            int r = i >> 5;
            int c = (i & 31) * 4;
            *(float4*)&obase[(size_t)(m0 + r) * LL_ + n0 + c] = nv;
        }
        return;
    }

    __shared__ uint8_t Qs[128 * QK8_STRIDE];
    __shared__ uint8_t Ks[128 * QK8_STRIDE];
    __shared__ int rmv[128], cmv[128];

    const uint8_t* qb = g_q8 + ((size_t)bh * LL_ + m0) * HS_;
    const uint8_t* kb = g_k8 + ((size_t)bh * LL_ + n0) * HS_;

    #pragma unroll
    for (int i = 0; i < 2; i++) {              // 512 x 16B chunks each
        int ch = t + 256 * i;
        int r = ch >> 2;
        int c = (ch & 3) * 16;
        cp16(smem_u32(&Qs[r * QK8_STRIDE + c]), qb + r * HS_ + c);
        cp16(smem_u32(&Ks[r * QK8_STRIDE + c]), kb + r * HS_ + c);
    }
    CP_COMMIT();
    if (t < 128) rmv[t] = am[b_ * LL_ + m0 + t];
    else         cmv[t - 128] = am[b_ * LL_ + n0 + (t - 128)];
    CP_WAIT0();
    __syncthreads();

    const int lane = t & 31;
    const int warp = t >> 5;
    const int g    = lane >> 2;
    const int tig  = lane & 3;
    const int wm   = warp >> 2;   // 0..1  (64 rows each)
    const int wn   = warp & 3;    // 0..3  (32 cols each)

    float acc[4][4][4];           // [mt][n8][4]
    #pragma unroll
    for (int mt = 0; mt < 4; mt++)
        #pragma unroll
        for (int j = 0; j < 4; j++)
            #pragma unroll
            for (int c = 0; c < 4; c++) acc[mt][j][c] = 0.0f;

    const int a_row  = lane & 15;
    const int a_coff = (lane >> 4) * 16;
    const int b_row  = (lane & 7) + 8 * (lane >> 4);
    const int b_coff = 16 * ((lane >> 3) & 1);
    const int aoff   = (wm * 64 + a_row) * QK8_STRIDE + a_coff;
    const int boff   = (wn * 32 + b_row) * QK8_STRIDE + b_coff;

    #pragma unroll
    for (int kk = 0; kk < 2; kk++) {
        const int k32 = kk * 32;
        uint32_t qf[4][4];
        #pragma unroll
        for (int mt = 0; mt < 4; mt++)
            ldsm_x4(qf[mt], &Qs[aoff + mt * 16 * QK8_STRIDE + k32]);
        #pragma unroll
        for (int nt = 0; nt < 2; nt++) {
            uint32_t kf[4];
            ldsm_x4(kf, &Ks[boff + nt * 16 * QK8_STRIDE + k32]);
            #pragma unroll
            for (int mt = 0; mt < 4; mt++) {
                mma_fp8(acc[mt][2 * nt],     qf[mt], &kf[0]);
                mma_fp8(acc[mt][2 * nt + 1], qf[mt], &kf[2]);
            }
        }
    }

    const bool diag = (tm == tn);
    #pragma unroll
    for (int mt = 0; mt < 4; mt++) {
        #pragma unroll
        for (int half = 0; half < 2; half++) {
            const int mi = wm * 64 + mt * 16 + g + half * 8;
            const int m  = m0 + mi;
            const bool rok = (rmv[mi] != 0);
            #pragma unroll
            for (int j = 0; j < 4; j++) {
                const int ni = wn * 32 + j * 8 + 2 * tig;
                const int n  = n0 + ni;
                float x0 = acc[mt][j][half * 2 + 0] * 0.125f;
                float x1 = acc[mt][j][half * 2 + 1] * 0.125f;
                bool k0 = !rok || cmv[ni] == 0;
                bool k1 = !rok || cmv[ni + 1] == 0;
                if (diag) { k0 |= (m > n); k1 |= (m > n + 1); }
                if (k0) x0 = NEG_INF_F;
                if (k1) x1 = NEG_INF_F;
                *(float2*)&obase[(size_t)m * LL_ + n] = make_float2(x0, x1);
            }
        }
    }
}

// ---------------------------------------------------------------------------
// Entry point
// ---------------------------------------------------------------------------
extern "C" void kernel_launch(void* const* d_in, const int* in_sizes, int n_in,
                              void* d_out, int out_size) {
    const float* inputs = (const float*)d_in[0];  // [8,512,768]
    const float* W      = (const float*)d_in[1];  // [768,1536]
    const float* bias   = (const float*)d_in[2];  // [1536]
    const int*   amask  = (const int*)d_in[3];    // [8,512]
    float* out = (float*)d_out;                   // [8,12,512,512]

    cudaFuncSetAttribute(gemm1_fp8,
                         cudaFuncAttributeMaxDynamicSharedMemorySize, G1_DSMEM);

    prep_all<<<NPREP_ + NTRB_, 256>>>(inputs, W);
    gemm1_fp8<<<dim3(OD_ / 128, M1_ / 128), 256, G1_DSMEM>>>(bias);
    attn_logits_fp8<<<dim3(LL_ / 128, LL_ / 128, BH_), 256>>>(amask, out);
}